// round 7
// baseline (speedup 1.0000x reference)
#include <cuda_runtime.h>
#include <cstdint>

// Degenerate conv (reference uses only x[:,0] and w[:,2]):
//   out(n,f,i,j) = bias[f] + sum_{a,b} w[f,2,a,b] * x[n,0,i+a,j+b]
//   x: (16,3,256,256) f32, w: (64,3,3,3) f32, b: (64,) f32
//   out: (16,64,254,254) f32
//
// Structure (champion R5 shape, more parallel): 2x2 output patch per thread
// (all stores warp-dense 256B/warp), filter dim split 8 ways (8 filters per
// thread) for maximum latency hiding. 6 blocks/SM forced via launch bounds.
#define NB     16
#define F_OUT  64
#define F_Q    8                  // filters per thread (8-way split)
#define Hh     256
#define Ww     256
#define HO     254
#define WO     254
#define IP     (HO / 2)           // 127 row-pairs (i even)
#define JP     (WO / 2)           // 127 col-pairs (j even)
#define N_SPATIAL (NB * IP * JP)  // 258064 spatial 2x2 patches
#define N_TOT     (N_SPATIAL * 8) // 2064512 threads

typedef unsigned long long u64;

// packed f32x2 FMA (Blackwell): d = a * w + c on both lanes
static __device__ __forceinline__ u64 ffma2(u64 a, u64 w, u64 c) {
    u64 d;
    asm("fma.rn.f32x2 %0, %1, %2, %3;" : "=l"(d) : "l"(a), "l"(w), "l"(c));
    return d;
}

static __device__ __forceinline__ u64 pack2(float lo, float hi) {
    u64 d;
    asm("mov.b64 %0, {%1, %2};" : "=l"(d) : "f"(lo), "f"(hi));
    return d;
}

__global__ __launch_bounds__(256, 6) void conv2dcq_kernel(
    const float* __restrict__ x,
    const float* __restrict__ w,
    const float* __restrict__ bias,
    float* __restrict__ out) {

    // Per-filter packed block of 5 ulonglong2 (16B):
    //   (bias,w0)(w1,w2)(w3,w4)(w5,w6)(w7,w8), each value duplicated (v,v).
    // 5 LDS.128 per filter.
    __shared__ ulonglong2 swb[F_OUT * 5];

    const int tid = threadIdx.x;
    {
        u64* sp = reinterpret_cast<u64*>(swb);
        for (int t = tid; t < F_OUT * 10; t += blockDim.x) {
            const int f = t / 10;
            const int k = t % 10;
            const float v = (k == 0) ? bias[f] : w[f * 27 + 18 + (k - 1)];
            sp[t] = pack2(v, v);
        }
    }
    __syncthreads();

    const int idx = blockIdx.x * blockDim.x + tid;
    if (idx >= N_TOT) return;

    const int q  = idx / N_SPATIAL;       // filter octant 0..7 (slowest dim)
    const int sp = idx - q * N_SPATIAL;
    const int f0 = q * F_Q;

    const int jp = sp % JP;               // fastest: warp-dense in j
    const int t2 = sp / JP;
    const int ip = t2 % IP;
    const int n  = t2 / IP;
    const int i  = ip * 2;        // even
    const int j  = jp * 2;        // even

    // Input channel 0: 4 rows x 4 cols for a 2x2 output patch.
    const float* xb = x + (size_t)n * 3 * Hh * Ww + (size_t)i * Ww + j;

    // P[r][b] = (x[i+r][j+b], x[i+r][j+b+1]) packed f32x2
    u64 P[4][3];
    #pragma unroll
    for (int r = 0; r < 4; r++) {
        const float2 lo = *reinterpret_cast<const float2*>(xb + (size_t)r * Ww);
        const float2 hi = *reinterpret_cast<const float2*>(xb + (size_t)r * Ww + 2);
        P[r][0] = pack2(lo.x, lo.y);
        P[r][1] = pack2(lo.y, hi.x);
        P[r][2] = pack2(hi.x, hi.y);
    }

    float* ob = out + (size_t)n * F_OUT * HO * WO
                    + (size_t)f0 * HO * WO
                    + (size_t)i * WO + j;

    const ulonglong2* wq = &swb[f0 * 5];

    #pragma unroll 4
    for (int f = 0; f < F_Q; f++) {
        // (bias, w0)
        const ulonglong2 q0 = wq[0];
        u64 a0 = q0.x, a1 = q0.x;
        a0 = ffma2(P[0][0], q0.y, a0);  a1 = ffma2(P[1][0], q0.y, a1);
        // (w1, w2)
        const ulonglong2 q1 = wq[1];
        a0 = ffma2(P[0][1], q1.x, a0);  a1 = ffma2(P[1][1], q1.x, a1);
        a0 = ffma2(P[0][2], q1.y, a0);  a1 = ffma2(P[1][2], q1.y, a1);
        // (w3, w4)
        const ulonglong2 q2 = wq[2];
        a0 = ffma2(P[1][0], q2.x, a0);  a1 = ffma2(P[2][0], q2.x, a1);
        a0 = ffma2(P[1][1], q2.y, a0);  a1 = ffma2(P[2][1], q2.y, a1);
        // (w5, w6)
        const ulonglong2 q3 = wq[3];
        a0 = ffma2(P[1][2], q3.x, a0);  a1 = ffma2(P[2][2], q3.x, a1);
        a0 = ffma2(P[2][0], q3.y, a0);  a1 = ffma2(P[3][0], q3.y, a1);
        // (w7, w8)
        const ulonglong2 q4 = wq[4];
        a0 = ffma2(P[2][1], q4.x, a0);  a1 = ffma2(P[3][1], q4.x, a1);
        a0 = ffma2(P[2][2], q4.y, a0);  a1 = ffma2(P[3][2], q4.y, a1);

        // warp-dense stores: consecutive threads -> consecutive 8B, 256B/warp
        *reinterpret_cast<u64*>(ob)      = a0;
        *reinterpret_cast<u64*>(ob + WO) = a1;

        ob += (size_t)HO * WO;
        wq += 5;
    }
}

extern "C" void kernel_launch(void* const* d_in, const int* in_sizes, int n_in,
                              void* d_out, int out_size) {
    const float* x    = (const float*)d_in[0];
    const float* w    = (const float*)d_in[1];
    const float* bias = (const float*)d_in[2];
    float* out        = (float*)d_out;

    const int block = 256;
    const int grid  = (N_TOT + block - 1) / block;   // 8065
    conv2dcq_kernel<<<grid, block>>>(x, w, bias, out);
}

// round 8
// speedup vs baseline: 1.5483x; 1.5483x over previous
#include <cuda_runtime.h>
#include <cstdint>

// Degenerate conv (reference uses only x[:,0] and w[:,2]):
//   out(n,f,i,j) = bias[f] + sum_{a,b} w[f,2,a,b] * x[n,0,i+a,j+b]
//   x: (16,3,256,256) f32, w: (64,3,3,3) f32, b: (64,) f32
//   out: (16,64,254,254) f32
//
// Structure: 2x2 output patch per thread (warp-dense 256B store instructions),
// filter dim split 4 ways via blockIdx.y (16 filters/thread). Weights + bias
// live in __constant__ memory with block-uniform addresses -> ULDC constant
// port, leaving the L1/LSU crossbar for input loads + output stores only.
#define NB     16
#define F_OUT  64
#define F_Q    16
#define Hh     256
#define Ww     256
#define HO     254
#define WO     254
#define IP     (HO / 2)           // 127 row-pairs (i even)
#define JP     (WO / 2)           // 127 col-pairs (j even)
#define N_SPATIAL (NB * IP * JP)  // 258064 spatial 2x2 patches

typedef unsigned long long u64;

__constant__ float c_w[F_OUT * 27];   // full weight tensor (we use [f][2][*])
__constant__ float c_b[F_OUT];

// packed f32x2 FMA (Blackwell): d = a * w + c on both lanes
static __device__ __forceinline__ u64 ffma2(u64 a, u64 w, u64 c) {
    u64 d;
    asm("fma.rn.f32x2 %0, %1, %2, %3;" : "=l"(d) : "l"(a), "l"(w), "l"(c));
    return d;
}

static __device__ __forceinline__ u64 pack2(float lo, float hi) {
    u64 d;
    asm("mov.b64 %0, {%1, %2};" : "=l"(d) : "f"(lo), "f"(hi));
    return d;
}

__global__ __launch_bounds__(256) void conv2dcq_kernel(
    const float* __restrict__ x,
    float* __restrict__ out) {

    const int sp = blockIdx.x * blockDim.x + threadIdx.x;
    if (sp >= N_SPATIAL) return;

    const int f0 = blockIdx.y * F_Q;      // block-uniform -> uniform LDC

    const int jp = sp % JP;               // fastest: warp-dense in j
    const int t2 = sp / JP;
    const int ip = t2 % IP;
    const int n  = t2 / IP;
    const int i  = ip * 2;        // even
    const int j  = jp * 2;        // even

    // Input channel 0: 4 rows x 4 cols for a 2x2 output patch.
    const float* xb = x + (size_t)n * 3 * Hh * Ww + (size_t)i * Ww + j;

    // P[r][b] = (x[i+r][j+b], x[i+r][j+b+1]) packed f32x2
    u64 P[4][3];
    #pragma unroll
    for (int r = 0; r < 4; r++) {
        const float2 lo = *reinterpret_cast<const float2*>(xb + (size_t)r * Ww);
        const float2 hi = *reinterpret_cast<const float2*>(xb + (size_t)r * Ww + 2);
        P[r][0] = pack2(lo.x, lo.y);
        P[r][1] = pack2(lo.y, hi.x);
        P[r][2] = pack2(hi.x, hi.y);
    }

    float* ob = out + (size_t)n * F_OUT * HO * WO
                    + (size_t)f0 * HO * WO
                    + (size_t)i * WO + j;

    #pragma unroll 4
    for (int f = f0; f < f0 + F_Q; f++) {
        const float* wf = c_w + f * 27 + 18;   // w[f, 2, :, :], uniform addr
        const float bv = c_b[f];
        u64 a0 = pack2(bv, bv);
        u64 a1 = a0;

        #pragma unroll
        for (int a = 0; a < 3; a++) {
            #pragma unroll
            for (int b = 0; b < 3; b++) {
                const float ws = wf[a * 3 + b];   // ULDC (constant port)
                const u64 wp = pack2(ws, ws);
                a0 = ffma2(P[a][b],     wp, a0);
                a1 = ffma2(P[a + 1][b], wp, a1);
            }
        }

        // warp-dense stores: consecutive threads -> consecutive 8B, 256B/warp
        *reinterpret_cast<u64*>(ob)      = a0;
        *reinterpret_cast<u64*>(ob + WO) = a1;
        ob += (size_t)HO * WO;
    }
}

extern "C" void kernel_launch(void* const* d_in, const int* in_sizes, int n_in,
                              void* d_out, int out_size) {
    const float* x    = (const float*)d_in[0];
    const float* w    = (const float*)d_in[1];
    const float* bias = (const float*)d_in[2];
    float* out        = (float*)d_out;

    // Stage weights/bias into constant memory (D2D async, graph-capturable).
    cudaMemcpyToSymbolAsync(c_w, w,    F_OUT * 27 * sizeof(float), 0,
                            cudaMemcpyDeviceToDevice, 0);
    cudaMemcpyToSymbolAsync(c_b, bias, F_OUT * sizeof(float), 0,
                            cudaMemcpyDeviceToDevice, 0);

    const int block = 256;
    dim3 grid((N_SPATIAL + block - 1) / block, F_OUT / F_Q);  // (1009, 4)
    conv2dcq_kernel<<<grid, block>>>(x, out);
}

// round 9
// speedup vs baseline: 1.6776x; 1.0835x over previous
#include <cuda_runtime.h>
#include <cstdint>

// Degenerate conv (reference uses only x[:,0] and w[:,2]):
//   out(n,f,i,j) = bias[f] + sum_{a,b} w[f,2,a,b] * x[n,0,i+a,j+b]
//   x: (16,3,256,256) f32, w: (64,3,3,3) f32, b: (64,) f32
//   out: (16,64,254,254) f32
//
// Structure: 2x2 output patch per thread, warp-dense STG.64 stores.
// Grid (127,16,4): blockIdx.x = row-pair, .y = batch, .z = filter quarter.
// Block = 128 threads = col-pair (zero div/mod index math).
// Weights in __constant__ (uniform LDC port, one CE staging node);
// bias via uniform __ldg (L1-resident).
#define NB     16
#define F_OUT  64
#define F_Q    16
#define Hh     256
#define Ww     256
#define HO     254
#define WO     254
#define IP     (HO / 2)           // 127 row-pairs
#define JP     (WO / 2)           // 127 col-pairs

typedef unsigned long long u64;

__constant__ float c_w[F_OUT * 27];   // full weight tensor (we use [f][2][*])

// packed f32x2 FMA (Blackwell): d = a * w + c on both lanes
static __device__ __forceinline__ u64 ffma2(u64 a, u64 w, u64 c) {
    u64 d;
    asm("fma.rn.f32x2 %0, %1, %2, %3;" : "=l"(d) : "l"(a), "l"(w), "l"(c));
    return d;
}

static __device__ __forceinline__ u64 pack2(float lo, float hi) {
    u64 d;
    asm("mov.b64 %0, {%1, %2};" : "=l"(d) : "f"(lo), "f"(hi));
    return d;
}

__global__ __launch_bounds__(128) void conv2dcq_kernel(
    const float* __restrict__ x,
    const float* __restrict__ bias,
    float* __restrict__ out) {

    const int jp = threadIdx.x;           // 0..127 (127 live)
    if (jp >= JP) return;

    const int ip = blockIdx.x;            // 0..126
    const int n  = blockIdx.y;            // 0..15
    const int f0 = blockIdx.z * F_Q;      // 0,16,32,48 (block-uniform)

    const int i = ip * 2;
    const int j = jp * 2;

    // Input channel 0: 4 rows x 4 cols for a 2x2 output patch.
    const float* xb = x + (size_t)n * 3 * Hh * Ww + (size_t)i * Ww + j;

    // P[r][b] = (x[i+r][j+b], x[i+r][j+b+1]) packed f32x2
    u64 P[4][3];
    #pragma unroll
    for (int r = 0; r < 4; r++) {
        const float2 lo = *reinterpret_cast<const float2*>(xb + (size_t)r * Ww);
        const float2 hi = *reinterpret_cast<const float2*>(xb + (size_t)r * Ww + 2);
        P[r][0] = pack2(lo.x, lo.y);
        P[r][1] = pack2(lo.y, hi.x);
        P[r][2] = pack2(hi.x, hi.y);
    }

    float* ob = out + (size_t)n * F_OUT * HO * WO
                    + (size_t)f0 * HO * WO
                    + (size_t)i * WO + j;

    #pragma unroll 4
    for (int f = f0; f < f0 + F_Q; f++) {
        const float* wf = c_w + f * 27 + 18;   // w[f, 2, :, :], uniform LDC
        const float bv = __ldg(bias + f);      // uniform, L1-resident
        u64 a0 = pack2(bv, bv);
        u64 a1 = a0;

        #pragma unroll
        for (int a = 0; a < 3; a++) {
            #pragma unroll
            for (int b = 0; b < 3; b++) {
                const float ws = wf[a * 3 + b];   // constant port
                const u64 wp = pack2(ws, ws);
                a0 = ffma2(P[a][b],     wp, a0);
                a1 = ffma2(P[a + 1][b], wp, a1);
            }
        }

        // warp-dense stores: consecutive threads -> consecutive 8B, 256B/warp
        *reinterpret_cast<u64*>(ob)      = a0;
        *reinterpret_cast<u64*>(ob + WO) = a1;
        ob += (size_t)HO * WO;
    }
}

extern "C" void kernel_launch(void* const* d_in, const int* in_sizes, int n_in,
                              void* d_out, int out_size) {
    const float* x    = (const float*)d_in[0];
    const float* w    = (const float*)d_in[1];
    const float* bias = (const float*)d_in[2];
    float* out        = (float*)d_out;

    // Single CE node: stage weights into constant memory (D2D, capturable).
    cudaMemcpyToSymbolAsync(c_w, w, F_OUT * 27 * sizeof(float), 0,
                            cudaMemcpyDeviceToDevice, 0);

    dim3 grid(IP, NB, F_OUT / F_Q);   // (127, 16, 4)
    conv2dcq_kernel<<<grid, 128>>>(x, bias, out);
}